// round 1
// baseline (speedup 1.0000x reference)
#include <cuda_runtime.h>

#define BB 4
#define SS 2048
#define DD 512
#define HH 8
#define HD 64

// q projected into [B, H, S, hd] layout (16 MB scratch)
__device__ float g_q[(size_t)BB * HH * SS * HD];

// ---------------------------------------------------------------------------
// Projection: q = x @ Wq   (M=8192, N=512, K=512), output re-laid as [B,H,S,hd]
// grid: (HH, M/64), block: 256 threads (16x16), 4x4 micro-tile, k-chunk 32
// ---------------------------------------------------------------------------
__global__ void proj_kernel(const float* __restrict__ x, const float* __restrict__ Wq) {
    __shared__ float Xs[32][68];   // k-major, transposed: Xs[k][row]
    __shared__ float Ws[32][68];   // Ws[k][n]
    const int tid = threadIdx.x;
    const int tx = tid & 15, ty = tid >> 4;
    const int m0 = blockIdx.y * 64;
    const int h  = blockIdx.x;            // n-tile == head

    float acc[4][4] = {};

    for (int kt = 0; kt < DD; kt += 32) {
        for (int i = tid; i < 512; i += 256) {          // 64x32 X tile as float4
            int r = i >> 3;
            int c = (i & 7) << 2;
            float4 v = *(const float4*)(x + (size_t)(m0 + r) * DD + kt + c);
            Xs[c    ][r] = v.x;
            Xs[c + 1][r] = v.y;
            Xs[c + 2][r] = v.z;
            Xs[c + 3][r] = v.w;
        }
        for (int i = tid; i < 512; i += 256) {          // 32x64 W tile
            int r = i >> 4;
            int c = (i & 15) << 2;
            *(float4*)&Ws[r][c] =
                *(const float4*)(Wq + (size_t)(kt + r) * DD + h * HD + c);
        }
        __syncthreads();

        #pragma unroll
        for (int kk = 0; kk < 32; kk++) {
            float4 a  = *(const float4*)&Xs[kk][ty * 4];
            float4 bv = *(const float4*)&Ws[kk][tx * 4];
            float av[4] = {a.x, a.y, a.z, a.w};
            float bb[4] = {bv.x, bv.y, bv.z, bv.w};
            #pragma unroll
            for (int i = 0; i < 4; i++)
                #pragma unroll
                for (int j = 0; j < 4; j++)
                    acc[i][j] = fmaf(av[i], bb[j], acc[i][j]);
        }
        __syncthreads();
    }

    const int b  = m0 / SS;   // 64-row tiles never straddle a batch boundary
    const int s0 = m0 % SS;
    float* dst = g_q + ((size_t)(b * HH + h) * SS + s0) * HD;
    #pragma unroll
    for (int i = 0; i < 4; i++) {
        float4 v = make_float4(acc[i][0], acc[i][1], acc[i][2], acc[i][3]);
        *(float4*)(dst + (size_t)(ty * 4 + i) * HD + tx * 4) = v;
    }
}

// ---------------------------------------------------------------------------
// Flash attention, Q=K=V=q. grid: (S/64, H, B), block: 256 threads.
// 64-row Q tile per CTA; loop over 64-row KV tiles (one shared copy, K==V).
// Online softmax; 4x4 register micro-tiles; shuffle row reductions.
// ---------------------------------------------------------------------------
__global__ void attn_kernel(float* __restrict__ out) {
    extern __shared__ float sm[];
    float* Qt = sm;                 // [64][68] d-major (transposed), pre-scaled by 1/8
    float* Kt = sm + 64 * 68;       // [64][68] d-major (transposed)
    float* KV = sm + 2 * 64 * 68;   // [64][68] k-major (row-major)
    float* Ps = sm + 3 * 64 * 68;   // [64][68] row-major probabilities

    const int tid = threadIdx.x;
    const int tx = tid & 15, ty = tid >> 4;
    const int qb = blockIdx.x, h = blockIdx.y, b = blockIdx.z;
    const float* qbase = g_q + (size_t)(b * HH + h) * SS * HD;

    // Load Q tile (transposed, pre-scaled by softmax scale 1/sqrt(64) = 1/8)
    for (int i = tid; i < 1024; i += 256) {
        int r = i >> 4;
        int c = (i & 15) << 2;
        float4 v = *(const float4*)(qbase + (size_t)(qb * 64 + r) * HD + c);
        Qt[(c    ) * 68 + r] = v.x * 0.125f;
        Qt[(c + 1) * 68 + r] = v.y * 0.125f;
        Qt[(c + 2) * 68 + r] = v.z * 0.125f;
        Qt[(c + 3) * 68 + r] = v.w * 0.125f;
    }

    float o[4][4] = {};
    float m_i[4] = {-1e30f, -1e30f, -1e30f, -1e30f};
    float l_i[4] = {};

    for (int kb = 0; kb < SS / 64; kb++) {
        __syncthreads();   // previous iter's Ps/KV readers done
        // Load KV tile (single copy; stored both k-major and d-major)
        for (int i = tid; i < 1024; i += 256) {
            int r = i >> 4;
            int c = (i & 15) << 2;
            float4 v = *(const float4*)(qbase + (size_t)(kb * 64 + r) * HD + c);
            *(float4*)&KV[r * 68 + c] = v;
            Kt[(c    ) * 68 + r] = v.x;
            Kt[(c + 1) * 68 + r] = v.y;
            Kt[(c + 2) * 68 + r] = v.z;
            Kt[(c + 3) * 68 + r] = v.w;
        }
        __syncthreads();

        // S = (Q/8) K^T : 4x4 micro-tile per thread
        float sc[4][4] = {};
        #pragma unroll 16
        for (int d = 0; d < 64; d++) {
            float4 qv = *(const float4*)&Qt[d * 68 + ty * 4];
            float4 kv = *(const float4*)&Kt[d * 68 + tx * 4];
            float qa[4] = {qv.x, qv.y, qv.z, qv.w};
            float ka[4] = {kv.x, kv.y, kv.z, kv.w};
            #pragma unroll
            for (int i = 0; i < 4; i++)
                #pragma unroll
                for (int j = 0; j < 4; j++)
                    sc[i][j] = fmaf(qa[i], ka[j], sc[i][j]);
        }

        // Online softmax per row (16 lanes per row within one warp half)
        #pragma unroll
        for (int i = 0; i < 4; i++) {
            float mx = fmaxf(fmaxf(sc[i][0], sc[i][1]), fmaxf(sc[i][2], sc[i][3]));
            #pragma unroll
            for (int off = 1; off < 16; off <<= 1)
                mx = fmaxf(mx, __shfl_xor_sync(0xffffffffu, mx, off));
            float mnew  = fmaxf(m_i[i], mx);
            float alpha = __expf(m_i[i] - mnew);
            m_i[i] = mnew;
            float rs = 0.f;
            #pragma unroll
            for (int j = 0; j < 4; j++) {
                sc[i][j] = __expf(sc[i][j] - mnew);
                rs += sc[i][j];
            }
            #pragma unroll
            for (int off = 1; off < 16; off <<= 1)
                rs += __shfl_xor_sync(0xffffffffu, rs, off);
            l_i[i] = l_i[i] * alpha + rs;
            #pragma unroll
            for (int j = 0; j < 4; j++) o[i][j] *= alpha;
        }

        // Stash P row-major (vectorized stores)
        #pragma unroll
        for (int i = 0; i < 4; i++)
            *(float4*)&Ps[(ty * 4 + i) * 68 + tx * 4] =
                make_float4(sc[i][0], sc[i][1], sc[i][2], sc[i][3]);
        __syncthreads();

        // O += P @ V  (V == KV tile, k-major). pa loads broadcast across lanes.
        #pragma unroll 8
        for (int k = 0; k < 64; k++) {
            float4 vv = *(const float4*)&KV[k * 68 + tx * 4];
            float va[4] = {vv.x, vv.y, vv.z, vv.w};
            float pa[4];
            #pragma unroll
            for (int i = 0; i < 4; i++) pa[i] = Ps[(ty * 4 + i) * 68 + k];
            #pragma unroll
            for (int i = 0; i < 4; i++)
                #pragma unroll
                for (int j = 0; j < 4; j++)
                    o[i][j] = fmaf(pa[i], va[j], o[i][j]);
        }
    }

    // Normalize and write out[b][s][h*64 + d]
    float* obase = out + ((size_t)b * SS + qb * 64) * DD + h * HD;
    #pragma unroll
    for (int i = 0; i < 4; i++) {
        float inv = 1.f / l_i[i];
        float4 v = make_float4(o[i][0] * inv, o[i][1] * inv,
                               o[i][2] * inv, o[i][3] * inv);
        *(float4*)(obase + (size_t)(ty * 4 + i) * DD + tx * 4) = v;
    }
}

extern "C" void kernel_launch(void* const* d_in, const int* in_sizes, int n_in,
                              void* d_out, int out_size) {
    const float* x  = (const float*)d_in[0];
    const float* Wq = (const float*)d_in[1];
    float* out = (float*)d_out;

    const int smem_bytes = 4 * 64 * 68 * 4;  // 69632 B
    cudaFuncSetAttribute(attn_kernel, cudaFuncAttributeMaxDynamicSharedMemorySize,
                         smem_bytes);

    proj_kernel<<<dim3(HH, (BB * SS) / 64), 256>>>(x, Wq);
    attn_kernel<<<dim3(SS / 64, HH, BB), 256, smem_bytes>>>(out);
}

// round 3
// speedup vs baseline: 2.0180x; 2.0180x over previous
#include <cuda_runtime.h>
#include <cuda_bf16.h>
#include <cstdint>

#define BB 4
#define SS 2048
#define DD 512
#define HH 8
#define HD 64

// q projected into [B, H, S, hd] layout (16 MB scratch)
__device__ float g_q[(size_t)BB * HH * SS * HD];

// ===========================================================================
// Projection: q = x @ Wq  (M=8192, N=512, K=512) -> g_q as [B,H,S,hd]
// ===========================================================================
__global__ void proj_kernel(const float* __restrict__ x, const float* __restrict__ Wq) {
    __shared__ float Xs[32][68];
    __shared__ float Ws[32][68];
    const int tid = threadIdx.x;
    const int tx = tid & 15, ty = tid >> 4;
    const int m0 = blockIdx.y * 64;
    const int h  = blockIdx.x;

    float acc[4][4] = {};

    for (int kt = 0; kt < DD; kt += 32) {
        for (int i = tid; i < 512; i += 256) {
            int r = i >> 3;
            int c = (i & 7) << 2;
            float4 v = *(const float4*)(x + (size_t)(m0 + r) * DD + kt + c);
            Xs[c    ][r] = v.x;
            Xs[c + 1][r] = v.y;
            Xs[c + 2][r] = v.z;
            Xs[c + 3][r] = v.w;
        }
        for (int i = tid; i < 512; i += 256) {
            int r = i >> 4;
            int c = (i & 15) << 2;
            *(float4*)&Ws[r][c] =
                *(const float4*)(Wq + (size_t)(kt + r) * DD + h * HD + c);
        }
        __syncthreads();

        #pragma unroll
        for (int kk = 0; kk < 32; kk++) {
            float4 a  = *(const float4*)&Xs[kk][ty * 4];
            float4 bv = *(const float4*)&Ws[kk][tx * 4];
            float av[4] = {a.x, a.y, a.z, a.w};
            float bb[4] = {bv.x, bv.y, bv.z, bv.w};
            #pragma unroll
            for (int i = 0; i < 4; i++)
                #pragma unroll
                for (int j = 0; j < 4; j++)
                    acc[i][j] = fmaf(av[i], bb[j], acc[i][j]);
        }
        __syncthreads();
    }

    const int b  = m0 / SS;
    const int s0 = m0 % SS;
    float* dst = g_q + ((size_t)(b * HH + h) * SS + s0) * HD;
    #pragma unroll
    for (int i = 0; i < 4; i++) {
        float4 v = make_float4(acc[i][0], acc[i][1], acc[i][2], acc[i][3]);
        *(float4*)(dst + (size_t)(ty * 4 + i) * HD + tx * 4) = v;
    }
}

// ===========================================================================
// mma.sync (HMMA) helpers — baseline PTX, compiles for plain sm_103
// ===========================================================================
__device__ __forceinline__ uint32_t smem_u32(const void* p) {
    uint32_t a;
    asm("{ .reg .u64 t; cvta.to.shared.u64 t, %1; cvt.u32.u64 %0, t; }"
        : "=r"(a) : "l"(p));
    return a;
}

#define LDSM_X4(r0, r1, r2, r3, addr)                                         \
    asm volatile("ldmatrix.sync.aligned.m8n8.x4.shared.b16 {%0,%1,%2,%3}, [%4];" \
                 : "=r"(r0), "=r"(r1), "=r"(r2), "=r"(r3) : "r"(addr))

__device__ __forceinline__ void mma16816(float* d, const uint32_t* a,
                                         uint32_t b0, uint32_t b1) {
    asm volatile(
        "mma.sync.aligned.m16n8k16.row.col.f32.bf16.bf16.f32 "
        "{%0,%1,%2,%3}, {%4,%5,%6,%7}, {%8,%9}, {%0,%1,%2,%3};"
        : "+f"(d[0]), "+f"(d[1]), "+f"(d[2]), "+f"(d[3])
        : "r"(a[0]), "r"(a[1]), "r"(a[2]), "r"(a[3]), "r"(b0), "r"(b1));
}

__device__ __forceinline__ uint32_t pack2(__nv_bfloat16 lo, __nv_bfloat16 hi) {
    return ((uint32_t)__bfloat16_as_ushort(hi) << 16) |
           (uint32_t)__bfloat16_as_ushort(lo);
}

// hi/lo bf16 split of a float pair -> packed bf16x2 words (lo element = 'a')
__device__ __forceinline__ void split2(float a, float b, uint32_t& hw, uint32_t& lw) {
    __nv_bfloat16 ah = __float2bfloat16(a);
    __nv_bfloat16 bh = __float2bfloat16(b);
    __nv_bfloat16 al = __float2bfloat16(a - __bfloat162float(ah));
    __nv_bfloat16 bl = __float2bfloat16(b - __bfloat162float(bh));
    hw = pack2(ah, bh);
    lw = pack2(al, bl);
}

// SMEM layout (bytes): Kh[128][72]bf16, Kl, Vth[64][136]bf16, Vtl
static constexpr uint32_t KPITCH = 144;    // 72 bf16 (row stride 4 banks)
static constexpr uint32_t VPITCH = 272;    // 136 bf16
static constexpr uint32_t P_KH = 0;
static constexpr uint32_t P_KL = 128 * KPITCH;            // 18432
static constexpr uint32_t P_VH = 2 * 128 * KPITCH;        // 36864
static constexpr uint32_t P_VL = P_VH + 64 * VPITCH;      // 54272
static constexpr uint32_t SMEM_BYTES = P_VL + 64 * VPITCH; // 71680

// Load a 128x64 f32 tile: split hi/lo bf16, write K-orientation (always)
// and V^T-orientation (if DO_V). 512 tasks: (kv-pair 0..63) x (d-group 0..7).
template <bool DO_V>
__device__ __forceinline__ void load_tile(char* smem, const float* __restrict__ src,
                                          int tid, float scale) {
    #pragma unroll
    for (int it = 0; it < 2; it++) {
        int task = tid + it * 256;
        int kvp = task & 63, dg = task >> 6;
        const float* p0 = src + (size_t)(2 * kvp) * HD + dg * 8;
        float4 a0 = *(const float4*)p0;
        float4 a1 = *(const float4*)(p0 + 4);
        float4 b0 = *(const float4*)(p0 + HD);
        float4 b1 = *(const float4*)(p0 + HD + 4);
        float fa[8] = {a0.x, a0.y, a0.z, a0.w, a1.x, a1.y, a1.z, a1.w};
        float fb[8] = {b0.x, b0.y, b0.z, b0.w, b1.x, b1.y, b1.z, b1.w};
        __nv_bfloat16 ah[8], al[8], bh[8], bl[8];
        #pragma unroll
        for (int j = 0; j < 8; j++) {
            float va = fa[j] * scale, vb = fb[j] * scale;
            ah[j] = __float2bfloat16(va);
            al[j] = __float2bfloat16(va - __bfloat162float(ah[j]));
            bh[j] = __float2bfloat16(vb);
            bl[j] = __float2bfloat16(vb - __bfloat162float(bh[j]));
        }
        uint32_t ra = (uint32_t)(2 * kvp) * KPITCH + dg * 16;
        uint32_t rb = ra + KPITCH;
        *(uint4*)(smem + P_KH + ra) = make_uint4(pack2(ah[0], ah[1]), pack2(ah[2], ah[3]),
                                                 pack2(ah[4], ah[5]), pack2(ah[6], ah[7]));
        *(uint4*)(smem + P_KH + rb) = make_uint4(pack2(bh[0], bh[1]), pack2(bh[2], bh[3]),
                                                 pack2(bh[4], bh[5]), pack2(bh[6], bh[7]));
        *(uint4*)(smem + P_KL + ra) = make_uint4(pack2(al[0], al[1]), pack2(al[2], al[3]),
                                                 pack2(al[4], al[5]), pack2(al[6], al[7]));
        *(uint4*)(smem + P_KL + rb) = make_uint4(pack2(bl[0], bl[1]), pack2(bl[2], bl[3]),
                                                 pack2(bl[4], bl[5]), pack2(bl[6], bl[7]));
        if (DO_V) {
            #pragma unroll
            for (int j = 0; j < 8; j++) {
                uint32_t vo = (uint32_t)(dg * 8 + j) * VPITCH + kvp * 4;
                *(uint32_t*)(smem + P_VH + vo) = pack2(ah[j], bh[j]);
                *(uint32_t*)(smem + P_VL + vo) = pack2(al[j], bl[j]);
            }
        }
    }
}

// ===========================================================================
// HMMA flash attention, Q=K=V=g_q. grid (S/128, H, B), 256 threads (8 warps).
// Warp w owns Q rows 16w..16w+15. O accumulates in registers across all KV
// tiles (no max-subtraction -> no rescale). 3-pass bf16 fp32 emulation.
// ===========================================================================
__global__ void __launch_bounds__(256, 1) attn_kernel(float* __restrict__ out) {
    extern __shared__ char smem[];
    const uint32_t sb = smem_u32(smem);
    const int tid = threadIdx.x;
    const int lane = tid & 31, w = tid >> 5;
    const int qb = blockIdx.x, h = blockIdx.y, b = blockIdx.z;
    const float* qbase = g_q + (size_t)(b * HH + h) * SS * HD;

    // ---- Q fragments (pre-scaled by 1/8), staged through K buffers ----
    uint32_t qh[4][4], ql[4][4];
    load_tile<false>(smem, qbase + (size_t)qb * 128 * HD, tid, 0.125f);
    __syncthreads();
    {
        uint32_t rowb = sb + (uint32_t)(w * 16 + (lane & 15)) * KPITCH
                           + (uint32_t)((lane >> 4) * 8) * 2;
        #pragma unroll
        for (int kc = 0; kc < 4; kc++) {
            LDSM_X4(qh[kc][0], qh[kc][1], qh[kc][2], qh[kc][3], rowb + kc * 32);
            LDSM_X4(ql[kc][0], ql[kc][1], ql[kc][2], ql[kc][3], rowb + P_KL + kc * 32);
        }
    }
    __syncthreads();

    float O[8][4] = {};
    float l0 = 0.f, l1 = 0.f;

    const uint32_t krow = sb + (uint32_t)(lane & 7) * KPITCH + (uint32_t)((lane >> 3) * 8) * 2;
    const uint32_t vrow = sb + P_VH + (uint32_t)(lane & 7) * VPITCH + (uint32_t)((lane >> 3) * 8) * 2;

    for (int kb = 0; kb < SS / 128; kb++) {
        load_tile<true>(smem, qbase + (size_t)kb * 128 * HD, tid, 1.0f);
        __syncthreads();

        // ---- S = Q K^T (3-pass) ----
        float S[16][4] = {};
        #pragma unroll
        for (int jj = 0; jj < 16; jj++) {
            uint32_t a = krow + (uint32_t)jj * 8 * KPITCH;
            uint32_t kh[8], kl[8];
            LDSM_X4(kh[0], kh[1], kh[2], kh[3], a);
            LDSM_X4(kh[4], kh[5], kh[6], kh[7], a + 64);
            LDSM_X4(kl[0], kl[1], kl[2], kl[3], a + P_KL);
            LDSM_X4(kl[4], kl[5], kl[6], kl[7], a + P_KL + 64);
            #pragma unroll
            for (int kc = 0; kc < 4; kc++) {
                mma16816(S[jj], qh[kc], kh[2 * kc], kh[2 * kc + 1]);
                mma16816(S[jj], qh[kc], kl[2 * kc], kl[2 * kc + 1]);
                mma16816(S[jj], ql[kc], kh[2 * kc], kh[2 * kc + 1]);
            }
        }

        // ---- softmax (no max-sub; scores bounded) + P frags in registers ----
        uint32_t ph[8][4], pl[8][4];
        #pragma unroll
        for (int jj = 0; jj < 16; jj++) {
            float e0 = __expf(S[jj][0]);
            float e1 = __expf(S[jj][1]);
            float e2 = __expf(S[jj][2]);
            float e3 = __expf(S[jj][3]);
            l0 += e0 + e1;
            l1 += e2 + e3;
            int kc = jj >> 1, o = (jj & 1) * 2;
            uint32_t hw01, lw01, hw23, lw23;
            split2(e0, e1, hw01, lw01);
            split2(e2, e3, hw23, lw23);
            ph[kc][o] = hw01; ph[kc][o + 1] = hw23;
            pl[kc][o] = lw01; pl[kc][o + 1] = lw23;
        }

        // ---- O += P V (3-pass) ----
        #pragma unroll
        for (int jj = 0; jj < 8; jj++) {
            uint32_t a = vrow + (uint32_t)jj * 8 * VPITCH;
            uint32_t bh[16], bl[16];
            LDSM_X4(bh[0],  bh[1],  bh[2],  bh[3],  a);
            LDSM_X4(bh[4],  bh[5],  bh[6],  bh[7],  a + 64);
            LDSM_X4(bh[8],  bh[9],  bh[10], bh[11], a + 128);
            LDSM_X4(bh[12], bh[13], bh[14], bh[15], a + 192);
            uint32_t al_ = a + (P_VL - P_VH);
            LDSM_X4(bl[0],  bl[1],  bl[2],  bl[3],  al_);
            LDSM_X4(bl[4],  bl[5],  bl[6],  bl[7],  al_ + 64);
            LDSM_X4(bl[8],  bl[9],  bl[10], bl[11], al_ + 128);
            LDSM_X4(bl[12], bl[13], bl[14], bl[15], al_ + 192);
            #pragma unroll
            for (int kc = 0; kc < 8; kc++) {
                mma16816(O[jj], ph[kc], bh[2 * kc], bh[2 * kc + 1]);
                mma16816(O[jj], ph[kc], bl[2 * kc], bl[2 * kc + 1]);
                mma16816(O[jj], pl[kc], bh[2 * kc], bh[2 * kc + 1]);
            }
        }
        __syncthreads();
    }

    // ---- epilogue: reduce l over the 4 lanes sharing each row, store ----
    l0 += __shfl_xor_sync(0xffffffffu, l0, 1);
    l0 += __shfl_xor_sync(0xffffffffu, l0, 2);
    l1 += __shfl_xor_sync(0xffffffffu, l1, 1);
    l1 += __shfl_xor_sync(0xffffffffu, l1, 2);
    float i0 = 1.f / l0, i1 = 1.f / l1;

    int r0 = qb * 128 + w * 16 + (lane >> 2);
    float* o0 = out + ((size_t)(b * SS + r0)) * DD + h * HD + (lane & 3) * 2;
    float* o1 = o0 + 8 * DD;
    #pragma unroll
    for (int jj = 0; jj < 8; jj++) {
        *(float2*)(o0 + jj * 8) = make_float2(O[jj][0] * i0, O[jj][1] * i0);
        *(float2*)(o1 + jj * 8) = make_float2(O[jj][2] * i1, O[jj][3] * i1);
    }
}

extern "C" void kernel_launch(void* const* d_in, const int* in_sizes, int n_in,
                              void* d_out, int out_size) {
    const float* x  = (const float*)d_in[0];
    const float* Wq = (const float*)d_in[1];
    float* out = (float*)d_out;

    cudaFuncSetAttribute(attn_kernel, cudaFuncAttributeMaxDynamicSharedMemorySize,
                         SMEM_BYTES);

    proj_kernel<<<dim3(HH, (BB * SS) / 64), 256>>>(x, Wq);
    attn_kernel<<<dim3(SS / 128, HH, BB), 256, SMEM_BYTES>>>(out);
}

// round 4
// speedup vs baseline: 2.1450x; 1.0629x over previous
#include <cuda_runtime.h>
#include <cuda_bf16.h>
#include <cstdint>

#define BB 4
#define SS 2048
#define DD 512
#define HH 8
#define HD 64

// Pre-split bf16 operands, written by proj epilogue.
// K-layout: [B*H][S][64]; V^T-layout: [B*H][64][S]
__device__ __nv_bfloat16 g_kh[(size_t)BB * HH * SS * HD];
__device__ __nv_bfloat16 g_kl[(size_t)BB * HH * SS * HD];
__device__ __nv_bfloat16 g_vh[(size_t)BB * HH * SS * HD];
__device__ __nv_bfloat16 g_vl[(size_t)BB * HH * SS * HD];

__device__ __forceinline__ uint32_t pack2(__nv_bfloat16 lo, __nv_bfloat16 hi) {
    return ((uint32_t)__bfloat16_as_ushort(hi) << 16) |
           (uint32_t)__bfloat16_as_ushort(lo);
}

// ===========================================================================
// Projection: q = x @ Wq, epilogue splits hi/lo bf16 and writes K + V^T layouts
// ===========================================================================
__global__ void proj_kernel(const float* __restrict__ x, const float* __restrict__ Wq) {
    __shared__ float Xs[32][68];
    __shared__ float Ws[32][68];
    const int tid = threadIdx.x;
    const int tx = tid & 15, ty = tid >> 4;
    const int m0 = blockIdx.y * 64;
    const int h  = blockIdx.x;

    float acc[4][4] = {};

    for (int kt = 0; kt < DD; kt += 32) {
        for (int i = tid; i < 512; i += 256) {
            int r = i >> 3;
            int c = (i & 7) << 2;
            float4 v = *(const float4*)(x + (size_t)(m0 + r) * DD + kt + c);
            Xs[c    ][r] = v.x;
            Xs[c + 1][r] = v.y;
            Xs[c + 2][r] = v.z;
            Xs[c + 3][r] = v.w;
        }
        for (int i = tid; i < 512; i += 256) {
            int r = i >> 4;
            int c = (i & 15) << 2;
            *(float4*)&Ws[r][c] =
                *(const float4*)(Wq + (size_t)(kt + r) * DD + h * HD + c);
        }
        __syncthreads();

        #pragma unroll
        for (int kk = 0; kk < 32; kk++) {
            float4 a  = *(const float4*)&Xs[kk][ty * 4];
            float4 bv = *(const float4*)&Ws[kk][tx * 4];
            float av[4] = {a.x, a.y, a.z, a.w};
            float bb[4] = {bv.x, bv.y, bv.z, bv.w};
            #pragma unroll
            for (int i = 0; i < 4; i++)
                #pragma unroll
                for (int j = 0; j < 4; j++)
                    acc[i][j] = fmaf(av[i], bb[j], acc[i][j]);
        }
        __syncthreads();
    }

    // epilogue: split + dual-layout store
    const int b  = m0 / SS;
    const int s0 = m0 % SS;
    const int bh = b * HH + h;

    __nv_bfloat16 hi[4][4], lo[4][4];
    #pragma unroll
    for (int i = 0; i < 4; i++)
        #pragma unroll
        for (int j = 0; j < 4; j++) {
            hi[i][j] = __float2bfloat16(acc[i][j]);
            lo[i][j] = __float2bfloat16(acc[i][j] - __bfloat162float(hi[i][j]));
        }

    // K-layout: row = s, pairs along d
    size_t kb_ = ((size_t)bh * SS + s0 + ty * 4) * HD + tx * 4;
    #pragma unroll
    for (int i = 0; i < 4; i++) {
        *(uint2*)&g_kh[kb_ + (size_t)i * HD] =
            make_uint2(pack2(hi[i][0], hi[i][1]), pack2(hi[i][2], hi[i][3]));
        *(uint2*)&g_kl[kb_ + (size_t)i * HD] =
            make_uint2(pack2(lo[i][0], lo[i][1]), pack2(lo[i][2], lo[i][3]));
    }
    // V^T-layout: row = d, pairs along s
    size_t vb_ = ((size_t)bh * HD + tx * 4) * SS + s0 + ty * 4;
    #pragma unroll
    for (int j = 0; j < 4; j++) {
        *(uint2*)&g_vh[vb_ + (size_t)j * SS] =
            make_uint2(pack2(hi[0][j], hi[1][j]), pack2(hi[2][j], hi[3][j]));
        *(uint2*)&g_vl[vb_ + (size_t)j * SS] =
            make_uint2(pack2(lo[0][j], lo[1][j]), pack2(lo[2][j], lo[3][j]));
    }
}

// ===========================================================================
// HMMA / cp.async helpers (baseline PTX, plain sm_103)
// ===========================================================================
__device__ __forceinline__ uint32_t smem_u32(const void* p) {
    uint32_t a;
    asm("{ .reg .u64 t; cvta.to.shared.u64 t, %1; cvt.u32.u64 %0, t; }"
        : "=r"(a) : "l"(p));
    return a;
}

#define LDSM_X4(r0, r1, r2, r3, addr)                                         \
    asm volatile("ldmatrix.sync.aligned.m8n8.x4.shared.b16 {%0,%1,%2,%3}, [%4];" \
                 : "=r"(r0), "=r"(r1), "=r"(r2), "=r"(r3) : "r"(addr))

__device__ __forceinline__ void mma16816(float* d, const uint32_t* a,
                                         uint32_t b0, uint32_t b1) {
    asm volatile(
        "mma.sync.aligned.m16n8k16.row.col.f32.bf16.bf16.f32 "
        "{%0,%1,%2,%3}, {%4,%5,%6,%7}, {%8,%9}, {%0,%1,%2,%3};"
        : "+f"(d[0]), "+f"(d[1]), "+f"(d[2]), "+f"(d[3])
        : "r"(a[0]), "r"(a[1]), "r"(a[2]), "r"(a[3]), "r"(b0), "r"(b1));
}

__device__ __forceinline__ void split2(float a, float b, uint32_t& hw, uint32_t& lw) {
    __nv_bfloat16 ah = __float2bfloat16(a);
    __nv_bfloat16 bh = __float2bfloat16(b);
    __nv_bfloat16 al = __float2bfloat16(a - __bfloat162float(ah));
    __nv_bfloat16 bl = __float2bfloat16(b - __bfloat162float(bh));
    hw = pack2(ah, bh);
    lw = pack2(al, bl);
}

#define CPA(dst, src) \
    asm volatile("cp.async.cg.shared.global [%0], [%1], 16;" :: "r"(dst), "l"(src))
#define CPC() asm volatile("cp.async.commit_group;" ::: "memory")
#define CPW(n) asm volatile("cp.async.wait_group %0;" :: "n"(n) : "memory")

// smem stage layout (bytes)
static constexpr uint32_t KPITCH = 144;
static constexpr uint32_t VPITCH = 272;
static constexpr uint32_t P_KH = 0;
static constexpr uint32_t P_KL = 128 * KPITCH;             // 18432
static constexpr uint32_t P_VH = 2 * 128 * KPITCH;         // 36864
static constexpr uint32_t P_VL = P_VH + 64 * VPITCH;       // 54272
static constexpr uint32_t STAGE = P_VL + 64 * VPITCH;      // 71680
static constexpr uint32_t SMEM_BYTES = 2 * STAGE;          // 143360

// async prefetch of one KV tile (bf16, pre-split) into a smem stage
__device__ __forceinline__ void prefetch_tile(uint32_t sbase,
                                              const __nv_bfloat16* kh,
                                              const __nv_bfloat16* kl,
                                              const __nv_bfloat16* vh,
                                              const __nv_bfloat16* vl,
                                              int tid) {
    #pragma unroll
    for (int it = 0; it < 4; it++) {              // K: 128 rows x 8 chunks
        int idx = tid + it * 256;
        int row = idx >> 3, c = idx & 7;
        uint32_t d = (uint32_t)row * KPITCH + c * 16;
        const char* s = (const char*)(kh + (size_t)row * HD + c * 8);
        CPA(sbase + P_KH + d, s);
        CPA(sbase + P_KL + d, (const char*)(kl + (size_t)row * HD + c * 8));
    }
    #pragma unroll
    for (int it = 0; it < 4; it++) {              // V^T: 64 rows x 16 chunks
        int idx = tid + it * 256;
        int row = idx >> 4, c = idx & 15;
        uint32_t d = (uint32_t)row * VPITCH + c * 16;
        CPA(sbase + P_VH + d, (const char*)(vh + (size_t)row * SS + c * 8));
        CPA(sbase + P_VL + d, (const char*)(vl + (size_t)row * SS + c * 8));
    }
}

// ===========================================================================
// HMMA flash attention, double-buffered cp.async. grid (S/128, H, B), 8 warps.
// ===========================================================================
__global__ void __launch_bounds__(256, 1) attn_kernel(float* __restrict__ out) {
    extern __shared__ char smem[];
    const uint32_t sb = smem_u32(smem);
    const int tid = threadIdx.x;
    const int lane = tid & 31, w = tid >> 5;
    const int qb = blockIdx.x, h = blockIdx.y, b = blockIdx.z;
    const int bh = b * HH + h;

    const __nv_bfloat16* khb = g_kh + (size_t)bh * SS * HD;
    const __nv_bfloat16* klb = g_kl + (size_t)bh * SS * HD;
    const __nv_bfloat16* vhb = g_vh + (size_t)bh * HD * SS;
    const __nv_bfloat16* vlb = g_vl + (size_t)bh * HD * SS;

    // ---- Q fragments straight from global (K-layout), unscaled ----
    uint32_t qh[4][4], ql[4][4];
    {
        const int r = lane >> 2, c2 = (lane & 3) * 2;
        const uint32_t* qhp = (const uint32_t*)(khb + (size_t)(qb * 128) * HD);
        const uint32_t* qlp = (const uint32_t*)(klb + (size_t)(qb * 128) * HD);
        #pragma unroll
        for (int kc = 0; kc < 4; kc++) {
            int base = (w * 16 + r) * HD + kc * 16 + c2;
            qh[kc][0] = qhp[(base          ) >> 1];
            qh[kc][1] = qhp[(base + 8 * HD ) >> 1];
            qh[kc][2] = qhp[(base + 8      ) >> 1];
            qh[kc][3] = qhp[(base + 8 * HD + 8) >> 1];
            ql[kc][0] = qlp[(base          ) >> 1];
            ql[kc][1] = qlp[(base + 8 * HD ) >> 1];
            ql[kc][2] = qlp[(base + 8      ) >> 1];
            ql[kc][3] = qlp[(base + 8 * HD + 8) >> 1];
        }
    }

    float O[8][4] = {};
    float l0 = 0.f, l1 = 0.f;

    const uint32_t krow = (uint32_t)(lane & 7) * KPITCH + (uint32_t)(lane >> 3) * 16;
    const uint32_t vrow = P_VH + (uint32_t)(lane & 7) * VPITCH + (uint32_t)(lane >> 3) * 16;

    // prefetch tile 0
    prefetch_tile(sb, khb, klb, vhb, vlb, tid);
    CPC();

    for (int kb = 0; kb < SS / 128; kb++) {
        const uint32_t st = sb + (uint32_t)(kb & 1) * STAGE;

        if (kb + 1 < SS / 128) {
            prefetch_tile(sb + (uint32_t)((kb + 1) & 1) * STAGE,
                          khb + (size_t)(kb + 1) * 128 * HD,
                          klb + (size_t)(kb + 1) * 128 * HD,
                          vhb + (size_t)(kb + 1) * 128,
                          vlb + (size_t)(kb + 1) * 128, tid);
            CPC();
            CPW(1);
        } else {
            CPW(0);
        }
        __syncthreads();

        // ---- S = Q K^T (3-pass) fused with softmax -> P fragments ----
        uint32_t ph[8][4], pl[8][4];
        #pragma unroll
        for (int jj = 0; jj < 16; jj++) {
            uint32_t a = st + krow + (uint32_t)jj * 8 * KPITCH;
            uint32_t kh_[8], kl_[8];
            LDSM_X4(kh_[0], kh_[1], kh_[2], kh_[3], a);
            LDSM_X4(kh_[4], kh_[5], kh_[6], kh_[7], a + 64);
            LDSM_X4(kl_[0], kl_[1], kl_[2], kl_[3], a + P_KL);
            LDSM_X4(kl_[4], kl_[5], kl_[6], kl_[7], a + P_KL + 64);
            float S4[4] = {};
            #pragma unroll
            for (int kc = 0; kc < 4; kc++) {
                mma16816(S4, qh[kc], kh_[2 * kc], kh_[2 * kc + 1]);
                mma16816(S4, qh[kc], kl_[2 * kc], kl_[2 * kc + 1]);
                mma16816(S4, ql[kc], kh_[2 * kc], kh_[2 * kc + 1]);
            }
            float e0 = __expf(S4[0] * 0.125f);
            float e1 = __expf(S4[1] * 0.125f);
            float e2 = __expf(S4[2] * 0.125f);
            float e3 = __expf(S4[3] * 0.125f);
            l0 += e0 + e1;
            l1 += e2 + e3;
            int kc = jj >> 1, o = (jj & 1) * 2;
            split2(e0, e1, ph[kc][o], pl[kc][o]);
            split2(e2, e3, ph[kc][o + 1], pl[kc][o + 1]);
        }

        // ---- O += P V (3-pass) ----
        #pragma unroll
        for (int jj = 0; jj < 8; jj++) {
            uint32_t a = st + vrow + (uint32_t)jj * 8 * VPITCH;
            uint32_t bh_[16], bl_[16];
            LDSM_X4(bh_[0],  bh_[1],  bh_[2],  bh_[3],  a);
            LDSM_X4(bh_[4],  bh_[5],  bh_[6],  bh_[7],  a + 64);
            LDSM_X4(bh_[8],  bh_[9],  bh_[10], bh_[11], a + 128);
            LDSM_X4(bh_[12], bh_[13], bh_[14], bh_[15], a + 192);
            uint32_t al_ = a + (P_VL - P_VH);
            LDSM_X4(bl_[0],  bl_[1],  bl_[2],  bl_[3],  al_);
            LDSM_X4(bl_[4],  bl_[5],  bl_[6],  bl_[7],  al_ + 64);
            LDSM_X4(bl_[8],  bl_[9],  bl_[10], bl_[11], al_ + 128);
            LDSM_X4(bl_[12], bl_[13], bl_[14], bl_[15], al_ + 192);
            #pragma unroll
            for (int kc = 0; kc < 8; kc++) {
                mma16816(O[jj], ph[kc], bh_[2 * kc], bh_[2 * kc + 1]);
                mma16816(O[jj], ph[kc], bl_[2 * kc], bl_[2 * kc + 1]);
                mma16816(O[jj], pl[kc], bh_[2 * kc], bh_[2 * kc + 1]);
            }
        }
        __syncthreads();
    }

    // ---- epilogue ----
    l0 += __shfl_xor_sync(0xffffffffu, l0, 1);
    l0 += __shfl_xor_sync(0xffffffffu, l0, 2);
    l1 += __shfl_xor_sync(0xffffffffu, l1, 1);
    l1 += __shfl_xor_sync(0xffffffffu, l1, 2);
    float i0 = 1.f / l0, i1 = 1.f / l1;

    int r0 = qb * 128 + w * 16 + (lane >> 2);
    float* o0 = out + ((size_t)(b * SS + r0)) * DD + h * HD + (lane & 3) * 2;
    float* o1 = o0 + 8 * DD;
    #pragma unroll
    for (int jj = 0; jj < 8; jj++) {
        *(float2*)(o0 + jj * 8) = make_float2(O[jj][0] * i0, O[jj][1] * i0);
        *(float2*)(o1 + jj * 8) = make_float2(O[jj][2] * i1, O[jj][3] * i1);
    }
}

extern "C" void kernel_launch(void* const* d_in, const int* in_sizes, int n_in,
                              void* d_out, int out_size) {
    const float* x  = (const float*)d_in[0];
    const float* Wq = (const float*)d_in[1];
    float* out = (float*)d_out;

    cudaFuncSetAttribute(attn_kernel, cudaFuncAttributeMaxDynamicSharedMemorySize,
                         SMEM_BYTES);

    proj_kernel<<<dim3(HH, (BB * SS) / 64), 256>>>(x, Wq);
    attn_kernel<<<dim3(SS / 128, HH, BB), 256, SMEM_BYTES>>>(out);
}

// round 5
// speedup vs baseline: 2.6766x; 1.2478x over previous
#include <cuda_runtime.h>
#include <cuda_bf16.h>
#include <cstdint>

#define BB 4
#define SS 2048
#define DD 512
#define HH 8
#define HD 64

// Pre-split bf16 operands, written by proj epilogue.
// K-layout: [B*H][S][64]; V^T-layout: [B*H][64][S]
__device__ __nv_bfloat16 g_kh[(size_t)BB * HH * SS * HD];
__device__ __nv_bfloat16 g_kl[(size_t)BB * HH * SS * HD];
__device__ __nv_bfloat16 g_vh[(size_t)BB * HH * SS * HD];
__device__ __nv_bfloat16 g_vl[(size_t)BB * HH * SS * HD];

__device__ __forceinline__ uint32_t pack2(__nv_bfloat16 lo, __nv_bfloat16 hi) {
    return ((uint32_t)__bfloat16_as_ushort(hi) << 16) |
           (uint32_t)__bfloat16_as_ushort(lo);
}

// ===========================================================================
// Projection: q = x @ Wq, epilogue splits hi/lo bf16 and writes K + V^T layouts
// ===========================================================================
__global__ void proj_kernel(const float* __restrict__ x, const float* __restrict__ Wq) {
    __shared__ float Xs[32][68];
    __shared__ float Ws[32][68];
    const int tid = threadIdx.x;
    const int tx = tid & 15, ty = tid >> 4;
    const int m0 = blockIdx.y * 64;
    const int h  = blockIdx.x;

    float acc[4][4] = {};

    for (int kt = 0; kt < DD; kt += 32) {
        for (int i = tid; i < 512; i += 256) {
            int r = i >> 3;
            int c = (i & 7) << 2;
            float4 v = *(const float4*)(x + (size_t)(m0 + r) * DD + kt + c);
            Xs[c    ][r] = v.x;
            Xs[c + 1][r] = v.y;
            Xs[c + 2][r] = v.z;
            Xs[c + 3][r] = v.w;
        }
        for (int i = tid; i < 512; i += 256) {
            int r = i >> 4;
            int c = (i & 15) << 2;
            *(float4*)&Ws[r][c] =
                *(const float4*)(Wq + (size_t)(kt + r) * DD + h * HD + c);
        }
        __syncthreads();

        #pragma unroll
        for (int kk = 0; kk < 32; kk++) {
            float4 a  = *(const float4*)&Xs[kk][ty * 4];
            float4 bv = *(const float4*)&Ws[kk][tx * 4];
            float av[4] = {a.x, a.y, a.z, a.w};
            float bb[4] = {bv.x, bv.y, bv.z, bv.w};
            #pragma unroll
            for (int i = 0; i < 4; i++)
                #pragma unroll
                for (int j = 0; j < 4; j++)
                    acc[i][j] = fmaf(av[i], bb[j], acc[i][j]);
        }
        __syncthreads();
    }

    const int b  = m0 / SS;
    const int s0 = m0 % SS;
    const int bh = b * HH + h;

    __nv_bfloat16 hi[4][4], lo[4][4];
    #pragma unroll
    for (int i = 0; i < 4; i++)
        #pragma unroll
        for (int j = 0; j < 4; j++) {
            hi[i][j] = __float2bfloat16(acc[i][j]);
            lo[i][j] = __float2bfloat16(acc[i][j] - __bfloat162float(hi[i][j]));
        }

    size_t kb_ = ((size_t)bh * SS + s0 + ty * 4) * HD + tx * 4;
    #pragma unroll
    for (int i = 0; i < 4; i++) {
        *(uint2*)&g_kh[kb_ + (size_t)i * HD] =
            make_uint2(pack2(hi[i][0], hi[i][1]), pack2(hi[i][2], hi[i][3]));
        *(uint2*)&g_kl[kb_ + (size_t)i * HD] =
            make_uint2(pack2(lo[i][0], lo[i][1]), pack2(lo[i][2], lo[i][3]));
    }
    size_t vb_ = ((size_t)bh * HD + tx * 4) * SS + s0 + ty * 4;
    #pragma unroll
    for (int j = 0; j < 4; j++) {
        *(uint2*)&g_vh[vb_ + (size_t)j * SS] =
            make_uint2(pack2(hi[0][j], hi[1][j]), pack2(hi[2][j], hi[3][j]));
        *(uint2*)&g_vl[vb_ + (size_t)j * SS] =
            make_uint2(pack2(lo[0][j], lo[1][j]), pack2(lo[2][j], lo[3][j]));
    }
}

// ===========================================================================
// HMMA / cp.async helpers (baseline PTX, plain sm_103)
// ===========================================================================
__device__ __forceinline__ uint32_t smem_u32(const void* p) {
    uint32_t a;
    asm("{ .reg .u64 t; cvta.to.shared.u64 t, %1; cvt.u32.u64 %0, t; }"
        : "=r"(a) : "l"(p));
    return a;
}

#define LDSM_X4(r0, r1, r2, r3, addr)                                         \
    asm volatile("ldmatrix.sync.aligned.m8n8.x4.shared.b16 {%0,%1,%2,%3}, [%4];" \
                 : "=r"(r0), "=r"(r1), "=r"(r2), "=r"(r3) : "r"(addr))

__device__ __forceinline__ void mma16816(float* d, const uint32_t* a,
                                         uint32_t b0, uint32_t b1) {
    asm volatile(
        "mma.sync.aligned.m16n8k16.row.col.f32.bf16.bf16.f32 "
        "{%0,%1,%2,%3}, {%4,%5,%6,%7}, {%8,%9}, {%0,%1,%2,%3};"
        : "+f"(d[0]), "+f"(d[1]), "+f"(d[2]), "+f"(d[3])
        : "r"(a[0]), "r"(a[1]), "r"(a[2]), "r"(a[3]), "r"(b0), "r"(b1));
}

#define CPA(dst, src) \
    asm volatile("cp.async.cg.shared.global [%0], [%1], 16;" :: "r"(dst), "l"(src))
#define CPC() asm volatile("cp.async.commit_group;" ::: "memory")
#define CPW(n) asm volatile("cp.async.wait_group %0;" :: "n"(n) : "memory")

// smem layout (bytes): K double-buffered (hi+lo per stage), V single (hi+lo)
static constexpr uint32_t KPITCH  = 144;
static constexpr uint32_t VPITCH  = 272;
static constexpr uint32_t KPLANE  = 128 * KPITCH;          // 18432
static constexpr uint32_t KSTAGE  = 2 * KPLANE;            // 36864 (hi, lo)
static constexpr uint32_t P_VH    = 2 * KSTAGE;            // 73728
static constexpr uint32_t VPLANE  = 64 * VPITCH;           // 17408
static constexpr uint32_t P_VL    = P_VH + VPLANE;         // 91136
static constexpr uint32_t SMEM_BYTES = P_VL + VPLANE;      // 108544 (2 CTAs/SM)

__device__ __forceinline__ void prefetch_k(uint32_t stage_base,
                                           const __nv_bfloat16* kh,
                                           const __nv_bfloat16* kl, int tid) {
    #pragma unroll
    for (int it = 0; it < 4; it++) {              // 128 rows x 8 chunks
        int idx = tid + it * 256;
        int row = idx >> 3, c = idx & 7;
        uint32_t d = (uint32_t)row * KPITCH + c * 16;
        CPA(stage_base + d, (const char*)(kh + (size_t)row * HD + c * 8));
        CPA(stage_base + KPLANE + d, (const char*)(kl + (size_t)row * HD + c * 8));
    }
}

__device__ __forceinline__ void prefetch_v(uint32_t sbase,
                                           const __nv_bfloat16* vh,
                                           const __nv_bfloat16* vl, int tid) {
    #pragma unroll
    for (int it = 0; it < 4; it++) {              // 64 rows x 16 chunks
        int idx = tid + it * 256;
        int row = idx >> 4, c = idx & 15;
        uint32_t d = (uint32_t)row * VPITCH + c * 16;
        CPA(sbase + P_VH + d, (const char*)(vh + (size_t)row * SS + c * 8));
        CPA(sbase + P_VL + d, (const char*)(vl + (size_t)row * SS + c * 8));
    }
}

// ===========================================================================
// HMMA flash attention. grid (S/128, H, B), 8 warps, 2 CTAs/SM.
// P kept hi-only (l accumulated from the same rounded p -> errors cancel).
// ===========================================================================
__global__ void __launch_bounds__(256, 2) attn_kernel(float* __restrict__ out) {
    extern __shared__ char smem[];
    const uint32_t sb = smem_u32(smem);
    const int tid = threadIdx.x;
    const int lane = tid & 31, w = tid >> 5;
    const int qb = blockIdx.x, h = blockIdx.y, b = blockIdx.z;
    const int bh = b * HH + h;
    const int NT = SS / 128;

    const __nv_bfloat16* khb = g_kh + (size_t)bh * SS * HD;
    const __nv_bfloat16* klb = g_kl + (size_t)bh * SS * HD;
    const __nv_bfloat16* vhb = g_vh + (size_t)bh * HD * SS;
    const __nv_bfloat16* vlb = g_vl + (size_t)bh * HD * SS;

    // prefetch K(0) into stage 0
    prefetch_k(sb, khb, klb, tid);
    CPC();

    // ---- Q fragments straight from global (K-layout) ----
    uint32_t qh[4][4], ql[4][4];
    {
        const int r = lane >> 2, c2 = (lane & 3) * 2;
        const uint32_t* qhp = (const uint32_t*)(khb + (size_t)(qb * 128) * HD);
        const uint32_t* qlp = (const uint32_t*)(klb + (size_t)(qb * 128) * HD);
        #pragma unroll
        for (int kc = 0; kc < 4; kc++) {
            int base = (w * 16 + r) * HD + kc * 16 + c2;
            qh[kc][0] = qhp[(base              ) >> 1];
            qh[kc][1] = qhp[(base + 8 * HD     ) >> 1];
            qh[kc][2] = qhp[(base + 8          ) >> 1];
            qh[kc][3] = qhp[(base + 8 * HD + 8 ) >> 1];
            ql[kc][0] = qlp[(base              ) >> 1];
            ql[kc][1] = qlp[(base + 8 * HD     ) >> 1];
            ql[kc][2] = qlp[(base + 8          ) >> 1];
            ql[kc][3] = qlp[(base + 8 * HD + 8 ) >> 1];
        }
    }

    float O[8][4] = {};
    float l0 = 0.f, l1 = 0.f;

    const uint32_t krow = (uint32_t)(lane & 7) * KPITCH + (uint32_t)(lane >> 3) * 16;
    const uint32_t vrow = P_VH + (uint32_t)(lane & 7) * VPITCH + (uint32_t)(lane >> 3) * 16;

    for (int kb = 0; kb < NT; kb++) {
        const uint32_t st = sb + (uint32_t)(kb & 1) * KSTAGE;

        __syncthreads();   // all warps done with V (and next K stage) from prev iter
        prefetch_v(sb, vhb + (size_t)kb * 128, vlb + (size_t)kb * 128, tid);
        CPC();
        if (kb + 1 < NT) {
            prefetch_k(sb + (uint32_t)((kb + 1) & 1) * KSTAGE,
                       khb + (size_t)(kb + 1) * 128 * HD,
                       klb + (size_t)(kb + 1) * 128 * HD, tid);
            CPC();
            CPW(2);        // K(kb) landed
        } else {
            CPW(1);
        }
        __syncthreads();

        // ---- S = Q K^T (3-pass) fused with softmax -> P (hi-only) ----
        uint32_t ph[8][4];
        #pragma unroll
        for (int jj = 0; jj < 16; jj++) {
            uint32_t a = st + krow + (uint32_t)jj * 8 * KPITCH;
            uint32_t kh_[8], kl_[8];
            LDSM_X4(kh_[0], kh_[1], kh_[2], kh_[3], a);
            LDSM_X4(kh_[4], kh_[5], kh_[6], kh_[7], a + 64);
            LDSM_X4(kl_[0], kl_[1], kl_[2], kl_[3], a + KPLANE);
            LDSM_X4(kl_[4], kl_[5], kl_[6], kl_[7], a + KPLANE + 64);
            float S4[4] = {};
            #pragma unroll
            for (int kc = 0; kc < 4; kc++) {
                mma16816(S4, qh[kc], kh_[2 * kc], kh_[2 * kc + 1]);
                mma16816(S4, qh[kc], kl_[2 * kc], kl_[2 * kc + 1]);
                mma16816(S4, ql[kc], kh_[2 * kc], kh_[2 * kc + 1]);
            }
            __nv_bfloat16 p0 = __float2bfloat16(__expf(S4[0] * 0.125f));
            __nv_bfloat16 p1 = __float2bfloat16(__expf(S4[1] * 0.125f));
            __nv_bfloat16 p2 = __float2bfloat16(__expf(S4[2] * 0.125f));
            __nv_bfloat16 p3 = __float2bfloat16(__expf(S4[3] * 0.125f));
            l0 += __bfloat162float(p0) + __bfloat162float(p1);
            l1 += __bfloat162float(p2) + __bfloat162float(p3);
            int kc = jj >> 1, o = (jj & 1) * 2;
            ph[kc][o]     = pack2(p0, p1);
            ph[kc][o + 1] = pack2(p2, p3);
        }

        if (kb + 1 < NT) CPW(1); else CPW(0);   // V(kb) landed
        __syncthreads();

        // ---- O += P V (2-pass: ph*vh + ph*vl), V frags in two groups ----
        #pragma unroll
        for (int jj = 0; jj < 8; jj++) {
            uint32_t a = sb + vrow + (uint32_t)jj * 8 * VPITCH;
            #pragma unroll
            for (int g = 0; g < 2; g++) {
                uint32_t ag = a + g * 128;
                uint32_t bh_[8], bl_[8];
                LDSM_X4(bh_[0], bh_[1], bh_[2], bh_[3], ag);
                LDSM_X4(bh_[4], bh_[5], bh_[6], bh_[7], ag + 64);
                LDSM_X4(bl_[0], bl_[1], bl_[2], bl_[3], ag + VPLANE);
                LDSM_X4(bl_[4], bl_[5], bl_[6], bl_[7], ag + VPLANE + 64);
                #pragma unroll
                for (int kc = 0; kc < 4; kc++) {
                    mma16816(O[jj], ph[g * 4 + kc], bh_[2 * kc], bh_[2 * kc + 1]);
                    mma16816(O[jj], ph[g * 4 + kc], bl_[2 * kc], bl_[2 * kc + 1]);
                }
            }
        }
    }

    // ---- epilogue ----
    l0 += __shfl_xor_sync(0xffffffffu, l0, 1);
    l0 += __shfl_xor_sync(0xffffffffu, l0, 2);
    l1 += __shfl_xor_sync(0xffffffffu, l1, 1);
    l1 += __shfl_xor_sync(0xffffffffu, l1, 2);
    float i0 = 1.f / l0, i1 = 1.f / l1;

    int r0 = qb * 128 + w * 16 + (lane >> 2);
    float* o0 = out + ((size_t)(b * SS + r0)) * DD + h * HD + (lane & 3) * 2;
    float* o1 = o0 + 8 * DD;
    #pragma unroll
    for (int jj = 0; jj < 8; jj++) {
        *(float2*)(o0 + jj * 8) = make_float2(O[jj][0] * i0, O[jj][1] * i0);
        *(float2*)(o1 + jj * 8) = make_float2(O[jj][2] * i1, O[jj][3] * i1);
    }
}

extern "C" void kernel_launch(void* const* d_in, const int* in_sizes, int n_in,
                              void* d_out, int out_size) {
    const float* x  = (const float*)d_in[0];
    const float* Wq = (const float*)d_in[1];
    float* out = (float*)d_out;

    cudaFuncSetAttribute(attn_kernel, cudaFuncAttributeMaxDynamicSharedMemorySize,
                         SMEM_BYTES);

    proj_kernel<<<dim3(HH, (BB * SS) / 64), 256>>>(x, Wq);
    attn_kernel<<<dim3(SS / 128, HH, BB), 256, SMEM_BYTES>>>(out);
}

// round 6
// speedup vs baseline: 3.1752x; 1.1863x over previous
#include <cuda_runtime.h>
#include <cuda_bf16.h>
#include <cstdint>

#define BB 4
#define SS 2048
#define DD 512
#define HH 8
#define HD 64

// Pre-split bf16 operands.
// x hi/lo: [M][512] (M=8192);  WqT hi/lo: [n][k] = [512][512]
__device__ __nv_bfloat16 g_xh[(size_t)BB * SS * DD];
__device__ __nv_bfloat16 g_xl[(size_t)BB * SS * DD];
__device__ __nv_bfloat16 g_wh[(size_t)DD * DD];
__device__ __nv_bfloat16 g_wl[(size_t)DD * DD];
// q hi/lo, K-layout [B*H][S][64] and V^T-layout [B*H][64][S]
__device__ __nv_bfloat16 g_kh[(size_t)BB * HH * SS * HD];
__device__ __nv_bfloat16 g_kl[(size_t)BB * HH * SS * HD];
__device__ __nv_bfloat16 g_vh[(size_t)BB * HH * SS * HD];
__device__ __nv_bfloat16 g_vl[(size_t)BB * HH * SS * HD];

__device__ __forceinline__ uint32_t pack2(__nv_bfloat16 lo, __nv_bfloat16 hi) {
    return ((uint32_t)__bfloat16_as_ushort(hi) << 16) |
           (uint32_t)__bfloat16_as_ushort(lo);
}

// ===========================================================================
// Conversion pre-kernels
// ===========================================================================
__global__ void conv_x(const float* __restrict__ x) {
    size_t i = ((size_t)blockIdx.x * 256 + threadIdx.x) * 4;
    float4 v = *(const float4*)(x + i);
    __nv_bfloat16 h0 = __float2bfloat16(v.x), h1 = __float2bfloat16(v.y);
    __nv_bfloat16 h2 = __float2bfloat16(v.z), h3 = __float2bfloat16(v.w);
    __nv_bfloat16 l0 = __float2bfloat16(v.x - __bfloat162float(h0));
    __nv_bfloat16 l1 = __float2bfloat16(v.y - __bfloat162float(h1));
    __nv_bfloat16 l2 = __float2bfloat16(v.z - __bfloat162float(h2));
    __nv_bfloat16 l3 = __float2bfloat16(v.w - __bfloat162float(h3));
    *(uint2*)&g_xh[i] = make_uint2(pack2(h0, h1), pack2(h2, h3));
    *(uint2*)&g_xl[i] = make_uint2(pack2(l0, l1), pack2(l2, l3));
}

__global__ void conv_w(const float* __restrict__ Wq) {
    __shared__ float t[32][33];
    const int bx = blockIdx.x * 32, by = blockIdx.y * 32;   // bx: n-tile, by: k-tile
    const int tx = threadIdx.x, ty = threadIdx.y;           // 32 x 8
    #pragma unroll
    for (int j = 0; j < 4; j++)
        t[ty + 8 * j][tx] = Wq[(size_t)(by + ty + 8 * j) * DD + bx + tx];
    __syncthreads();
    #pragma unroll
    for (int j = 0; j < 4; j++) {
        float v = t[tx][ty + 8 * j];
        __nv_bfloat16 h = __float2bfloat16(v);
        __nv_bfloat16 l = __float2bfloat16(v - __bfloat162float(h));
        size_t o = (size_t)(bx + ty + 8 * j) * DD + by + tx;
        g_wh[o] = h;
        g_wl[o] = l;
    }
}

// ===========================================================================
// HMMA / cp.async helpers (baseline PTX, plain sm_103)
// ===========================================================================
__device__ __forceinline__ uint32_t smem_u32(const void* p) {
    uint32_t a;
    asm("{ .reg .u64 t; cvta.to.shared.u64 t, %1; cvt.u32.u64 %0, t; }"
        : "=r"(a) : "l"(p));
    return a;
}

#define LDSM_X4(r0, r1, r2, r3, addr)                                         \
    asm volatile("ldmatrix.sync.aligned.m8n8.x4.shared.b16 {%0,%1,%2,%3}, [%4];" \
                 : "=r"(r0), "=r"(r1), "=r"(r2), "=r"(r3) : "r"(addr))

__device__ __forceinline__ void mma16816(float* d, const uint32_t* a,
                                         uint32_t b0, uint32_t b1) {
    asm volatile(
        "mma.sync.aligned.m16n8k16.row.col.f32.bf16.bf16.f32 "
        "{%0,%1,%2,%3}, {%4,%5,%6,%7}, {%8,%9}, {%0,%1,%2,%3};"
        : "+f"(d[0]), "+f"(d[1]), "+f"(d[2]), "+f"(d[3])
        : "r"(a[0]), "r"(a[1]), "r"(a[2]), "r"(a[3]), "r"(b0), "r"(b1));
}

#define CPA(dst, src) \
    asm volatile("cp.async.cg.shared.global [%0], [%1], 16;" :: "r"(dst), "l"(src))
#define CPC() asm volatile("cp.async.commit_group;" ::: "memory")
#define CPW(n) asm volatile("cp.async.wait_group %0;" :: "n"(n) : "memory")

// ===========================================================================
// Projection GEMM on HMMA: q = x @ Wq per head, 3-pass bf16.
// grid (64, 8): 128 M-rows x one head (64 N). K=512 in 8 chunks, double-buffered.
// Epilogue: split hi/lo, write K-layout + V^T-layout.
// ===========================================================================
static constexpr uint32_t JPITCH  = 144;
static constexpr uint32_t JXPLANE = 128 * JPITCH;             // 18432
static constexpr uint32_t JP_WH   = 2 * JXPLANE;              // 36864
static constexpr uint32_t JWPLANE = 64 * JPITCH;              // 9216
static constexpr uint32_t JSTAGE  = JP_WH + 2 * JWPLANE;      // 55296
static constexpr uint32_t PROJ_SMEM = 2 * JSTAGE;             // 110592

__device__ __forceinline__ void proj_prefetch(uint32_t st, int m0, int n0, int kc,
                                              int tid) {
    const __nv_bfloat16* xh = g_xh + (size_t)m0 * DD + kc * 64;
    const __nv_bfloat16* xl = g_xl + (size_t)m0 * DD + kc * 64;
    #pragma unroll
    for (int it = 0; it < 4; it++) {              // X: 128 rows x 8 x 16B
        int idx = tid + it * 256;
        int row = idx >> 3, c = idx & 7;
        uint32_t d = (uint32_t)row * JPITCH + c * 16;
        CPA(st + d, (const char*)(xh + (size_t)row * DD + c * 8));
        CPA(st + JXPLANE + d, (const char*)(xl + (size_t)row * DD + c * 8));
    }
    const __nv_bfloat16* wh = g_wh + (size_t)n0 * DD + kc * 64;
    const __nv_bfloat16* wl = g_wl + (size_t)n0 * DD + kc * 64;
    #pragma unroll
    for (int it = 0; it < 2; it++) {              // W: 64 rows x 8 x 16B
        int idx = tid + it * 256;
        int row = idx >> 3, c = idx & 7;
        uint32_t d = (uint32_t)row * JPITCH + c * 16;
        CPA(st + JP_WH + d, (const char*)(wh + (size_t)row * DD + c * 8));
        CPA(st + JP_WH + JWPLANE + d, (const char*)(wl + (size_t)row * DD + c * 8));
    }
}

__global__ void __launch_bounds__(256, 2) proj_hmma(int dummy) {
    extern __shared__ char smem[];
    const uint32_t sb = smem_u32(smem);
    const int tid = threadIdx.x;
    const int lane = tid & 31, w = tid >> 5;
    const int m0 = blockIdx.x * 128;
    const int h  = blockIdx.y;
    const int n0 = h * 64;

    proj_prefetch(sb, m0, n0, 0, tid);
    CPC();

    float acc[8][4] = {};
    const uint32_t arow = (uint32_t)(w * 16 + (lane & 15)) * JPITCH
                        + (uint32_t)(lane >> 4) * 16;
    const uint32_t wrow = JP_WH + (uint32_t)(lane & 7) * JPITCH
                        + (uint32_t)(lane >> 3) * 16;

    for (int kc = 0; kc < 8; kc++) {
        const uint32_t st = sb + (uint32_t)(kc & 1) * JSTAGE;
        if (kc + 1 < 8) {
            proj_prefetch(sb + (uint32_t)((kc + 1) & 1) * JSTAGE, m0, n0, kc + 1, tid);
            CPC();
            CPW(1);
        } else {
            CPW(0);
        }
        __syncthreads();

        uint32_t ah[4][4], al[4][4];
        #pragma unroll
        for (int i = 0; i < 4; i++) {
            LDSM_X4(ah[i][0], ah[i][1], ah[i][2], ah[i][3], st + arow + i * 32);
            LDSM_X4(al[i][0], al[i][1], al[i][2], al[i][3],
                    st + arow + JXPLANE + i * 32);
        }
        #pragma unroll
        for (int jj = 0; jj < 8; jj++) {
            uint32_t a = st + wrow + (uint32_t)jj * 8 * JPITCH;
            uint32_t bh_[8], bl_[8];
            LDSM_X4(bh_[0], bh_[1], bh_[2], bh_[3], a);
            LDSM_X4(bh_[4], bh_[5], bh_[6], bh_[7], a + 64);
            LDSM_X4(bl_[0], bl_[1], bl_[2], bl_[3], a + JWPLANE);
            LDSM_X4(bl_[4], bl_[5], bl_[6], bl_[7], a + JWPLANE + 64);
            #pragma unroll
            for (int i = 0; i < 4; i++) {
                mma16816(acc[jj], ah[i], bh_[2 * i], bh_[2 * i + 1]);
                mma16816(acc[jj], ah[i], bl_[2 * i], bl_[2 * i + 1]);
                mma16816(acc[jj], al[i], bh_[2 * i], bh_[2 * i + 1]);
            }
        }
        __syncthreads();
    }

    // ---- epilogue: split hi/lo; write K-layout + V^T-layout ----
    const int r0g = m0 + w * 16 + (lane >> 2);
    const int b   = r0g >> 11;
    const int s0  = r0g & (SS - 1);
    const int bh_i = b * HH + h;
    const int c2  = (lane & 3) * 2;

    #pragma unroll
    for (int jj = 0; jj < 8; jj++) {
        int c = jj * 8 + c2;
        __nv_bfloat16 h0 = __float2bfloat16(acc[jj][0]);
        __nv_bfloat16 h1 = __float2bfloat16(acc[jj][1]);
        __nv_bfloat16 h2 = __float2bfloat16(acc[jj][2]);
        __nv_bfloat16 h3 = __float2bfloat16(acc[jj][3]);
        __nv_bfloat16 l0 = __float2bfloat16(acc[jj][0] - __bfloat162float(h0));
        __nv_bfloat16 l1 = __float2bfloat16(acc[jj][1] - __bfloat162float(h1));
        __nv_bfloat16 l2 = __float2bfloat16(acc[jj][2] - __bfloat162float(h2));
        __nv_bfloat16 l3 = __float2bfloat16(acc[jj][3] - __bfloat162float(h3));

        size_t ka = ((size_t)bh_i * SS + s0) * HD + c;
        *(uint32_t*)&g_kh[ka] = pack2(h0, h1);
        *(uint32_t*)&g_kl[ka] = pack2(l0, l1);
        *(uint32_t*)&g_kh[ka + 8 * HD] = pack2(h2, h3);
        *(uint32_t*)&g_kl[ka + 8 * HD] = pack2(l2, l3);

        size_t va = ((size_t)bh_i * HD + c) * SS + s0;
        g_vh[va] = h0;           g_vl[va] = l0;
        g_vh[va + SS] = h1;      g_vl[va + SS] = l1;
        g_vh[va + 8] = h2;       g_vl[va + 8] = l2;
        g_vh[va + SS + 8] = h3;  g_vl[va + SS + 8] = l3;
    }
}

// ===========================================================================
// Attention (unchanged from round 5): HMMA flash, 2 CTAs/SM, P hi-only
// ===========================================================================
static constexpr uint32_t KPITCH  = 144;
static constexpr uint32_t VPITCH  = 272;
static constexpr uint32_t KPLANE  = 128 * KPITCH;
static constexpr uint32_t KSTAGE  = 2 * KPLANE;
static constexpr uint32_t P_VH    = 2 * KSTAGE;
static constexpr uint32_t VPLANE  = 64 * VPITCH;
static constexpr uint32_t P_VL    = P_VH + VPLANE;
static constexpr uint32_t SMEM_BYTES = P_VL + VPLANE;      // 108544

__device__ __forceinline__ void prefetch_k(uint32_t stage_base,
                                           const __nv_bfloat16* kh,
                                           const __nv_bfloat16* kl, int tid) {
    #pragma unroll
    for (int it = 0; it < 4; it++) {
        int idx = tid + it * 256;
        int row = idx >> 3, c = idx & 7;
        uint32_t d = (uint32_t)row * KPITCH + c * 16;
        CPA(stage_base + d, (const char*)(kh + (size_t)row * HD + c * 8));
        CPA(stage_base + KPLANE + d, (const char*)(kl + (size_t)row * HD + c * 8));
    }
}

__device__ __forceinline__ void prefetch_v(uint32_t sbase,
                                           const __nv_bfloat16* vh,
                                           const __nv_bfloat16* vl, int tid) {
    #pragma unroll
    for (int it = 0; it < 4; it++) {
        int idx = tid + it * 256;
        int row = idx >> 4, c = idx & 15;
        uint32_t d = (uint32_t)row * VPITCH + c * 16;
        CPA(sbase + P_VH + d, (const char*)(vh + (size_t)row * SS + c * 8));
        CPA(sbase + P_VL + d, (const char*)(vl + (size_t)row * SS + c * 8));
    }
}

__global__ void __launch_bounds__(256, 2) attn_kernel(float* __restrict__ out) {
    extern __shared__ char smem[];
    const uint32_t sb = smem_u32(smem);
    const int tid = threadIdx.x;
    const int lane = tid & 31, w = tid >> 5;
    const int qb = blockIdx.x, h = blockIdx.y, b = blockIdx.z;
    const int bh = b * HH + h;
    const int NT = SS / 128;

    const __nv_bfloat16* khb = g_kh + (size_t)bh * SS * HD;
    const __nv_bfloat16* klb = g_kl + (size_t)bh * SS * HD;
    const __nv_bfloat16* vhb = g_vh + (size_t)bh * HD * SS;
    const __nv_bfloat16* vlb = g_vl + (size_t)bh * HD * SS;

    prefetch_k(sb, khb, klb, tid);
    CPC();

    uint32_t qh[4][4], ql[4][4];
    {
        const int r = lane >> 2, c2 = (lane & 3) * 2;
        const uint32_t* qhp = (const uint32_t*)(khb + (size_t)(qb * 128) * HD);
        const uint32_t* qlp = (const uint32_t*)(klb + (size_t)(qb * 128) * HD);
        #pragma unroll
        for (int kc = 0; kc < 4; kc++) {
            int base = (w * 16 + r) * HD + kc * 16 + c2;
            qh[kc][0] = qhp[(base              ) >> 1];
            qh[kc][1] = qhp[(base + 8 * HD     ) >> 1];
            qh[kc][2] = qhp[(base + 8          ) >> 1];
            qh[kc][3] = qhp[(base + 8 * HD + 8 ) >> 1];
            ql[kc][0] = qlp[(base              ) >> 1];
            ql[kc][1] = qlp[(base + 8 * HD     ) >> 1];
            ql[kc][2] = qlp[(base + 8          ) >> 1];
            ql[kc][3] = qlp[(base + 8 * HD + 8 ) >> 1];
        }
    }

    float O[8][4] = {};
    float l0 = 0.f, l1 = 0.f;

    const uint32_t krow = (uint32_t)(lane & 7) * KPITCH + (uint32_t)(lane >> 3) * 16;
    const uint32_t vrow = P_VH + (uint32_t)(lane & 7) * VPITCH + (uint32_t)(lane >> 3) * 16;

    for (int kb = 0; kb < NT; kb++) {
        const uint32_t st = sb + (uint32_t)(kb & 1) * KSTAGE;

        __syncthreads();
        prefetch_v(sb, vhb + (size_t)kb * 128, vlb + (size_t)kb * 128, tid);
        CPC();
        if (kb + 1 < NT) {
            prefetch_k(sb + (uint32_t)((kb + 1) & 1) * KSTAGE,
                       khb + (size_t)(kb + 1) * 128 * HD,
                       klb + (size_t)(kb + 1) * 128 * HD, tid);
            CPC();
            CPW(2);
        } else {
            CPW(1);
        }
        __syncthreads();

        uint32_t ph[8][4];
        #pragma unroll
        for (int jj = 0; jj < 16; jj++) {
            uint32_t a = st + krow + (uint32_t)jj * 8 * KPITCH;
            uint32_t kh_[8], kl_[8];
            LDSM_X4(kh_[0], kh_[1], kh_[2], kh_[3], a);
            LDSM_X4(kh_[4], kh_[5], kh_[6], kh_[7], a + 64);
            LDSM_X4(kl_[0], kl_[1], kl_[2], kl_[3], a + KPLANE);
            LDSM_X4(kl_[4], kl_[5], kl_[6], kl_[7], a + KPLANE + 64);
            float S4[4] = {};
            #pragma unroll
            for (int kc = 0; kc < 4; kc++) {
                mma16816(S4, qh[kc], kh_[2 * kc], kh_[2 * kc + 1]);
                mma16816(S4, qh[kc], kl_[2 * kc], kl_[2 * kc + 1]);
                mma16816(S4, ql[kc], kh_[2 * kc], kh_[2 * kc + 1]);
            }
            __nv_bfloat16 p0 = __float2bfloat16(__expf(S4[0] * 0.125f));
            __nv_bfloat16 p1 = __float2bfloat16(__expf(S4[1] * 0.125f));
            __nv_bfloat16 p2 = __float2bfloat16(__expf(S4[2] * 0.125f));
            __nv_bfloat16 p3 = __float2bfloat16(__expf(S4[3] * 0.125f));
            l0 += __bfloat162float(p0) + __bfloat162float(p1);
            l1 += __bfloat162float(p2) + __bfloat162float(p3);
            int kc = jj >> 1, o = (jj & 1) * 2;
            ph[kc][o]     = pack2(p0, p1);
            ph[kc][o + 1] = pack2(p2, p3);
        }

        if (kb + 1 < NT) CPW(1); else CPW(0);
        __syncthreads();

        #pragma unroll
        for (int jj = 0; jj < 8; jj++) {
            uint32_t a = sb + vrow + (uint32_t)jj * 8 * VPITCH;
            #pragma unroll
            for (int g = 0; g < 2; g++) {
                uint32_t ag = a + g * 128;
                uint32_t bh_[8], bl_[8];
                LDSM_X4(bh_[0], bh_[1], bh_[2], bh_[3], ag);
                LDSM_X4(bh_[4], bh_[5], bh_[6], bh_[7], ag + 64);
                LDSM_X4(bl_[0], bl_[1], bl_[2], bl_[3], ag + VPLANE);
                LDSM_X4(bl_[4], bl_[5], bl_[6], bl_[7], ag + VPLANE + 64);
                #pragma unroll
                for (int kc = 0; kc < 4; kc++) {
                    mma16816(O[jj], ph[g * 4 + kc], bh_[2 * kc], bh_[2 * kc + 1]);
                    mma16816(O[jj], ph[g * 4 + kc], bl_[2 * kc], bl_[2 * kc + 1]);
                }
            }
        }
    }

    l0 += __shfl_xor_sync(0xffffffffu, l0, 1);
    l0 += __shfl_xor_sync(0xffffffffu, l0, 2);
    l1 += __shfl_xor_sync(0xffffffffu, l1, 1);
    l1 += __shfl_xor_sync(0xffffffffu, l1, 2);
    float i0 = 1.f / l0, i1 = 1.f / l1;

    int r0 = qb * 128 + w * 16 + (lane >> 2);
    float* o0 = out + ((size_t)(b * SS + r0)) * DD + h * HD + (lane & 3) * 2;
    float* o1 = o0 + 8 * DD;
    #pragma unroll
    for (int jj = 0; jj < 8; jj++) {
        *(float2*)(o0 + jj * 8) = make_float2(O[jj][0] * i0, O[jj][1] * i0);
        *(float2*)(o1 + jj * 8) = make_float2(O[jj][2] * i1, O[jj][3] * i1);
    }
}

extern "C" void kernel_launch(void* const* d_in, const int* in_sizes, int n_in,
                              void* d_out, int out_size) {
    const float* x  = (const float*)d_in[0];
    const float* Wq = (const float*)d_in[1];
    float* out = (float*)d_out;

    cudaFuncSetAttribute(proj_hmma, cudaFuncAttributeMaxDynamicSharedMemorySize,
                         PROJ_SMEM);
    cudaFuncSetAttribute(attn_kernel, cudaFuncAttributeMaxDynamicSharedMemorySize,
                         SMEM_BYTES);

    conv_x<<<(BB * SS * DD) / (256 * 4), 256>>>(x);
    conv_w<<<dim3(DD / 32, DD / 32), dim3(32, 8)>>>(Wq);
    proj_hmma<<<dim3((BB * SS) / 128, HH), 256, PROJ_SMEM>>>(0);
    attn_kernel<<<dim3(SS / 128, HH, BB), 256, SMEM_BYTES>>>(out);
}

// round 7
// speedup vs baseline: 3.4545x; 1.0880x over previous
#include <cuda_runtime.h>
#include <cuda_bf16.h>
#include <cstdint>

#define BB 4
#define SS 2048
#define DD 512
#define HH 8
#define HD 64

// Pre-split bf16 operands.
__device__ __nv_bfloat16 g_xh[(size_t)BB * SS * DD];
__device__ __nv_bfloat16 g_xl[(size_t)BB * SS * DD];
__device__ __nv_bfloat16 g_wh[(size_t)DD * DD];
__device__ __nv_bfloat16 g_wl[(size_t)DD * DD];
// q hi/lo, K-layout only: [B*H][S][64] (PV uses ldmatrix.trans on the same data)
__device__ __nv_bfloat16 g_kh[(size_t)BB * HH * SS * HD];
__device__ __nv_bfloat16 g_kl[(size_t)BB * HH * SS * HD];

__device__ __forceinline__ uint32_t pack2(__nv_bfloat16 lo, __nv_bfloat16 hi) {
    return ((uint32_t)__bfloat16_as_ushort(hi) << 16) |
           (uint32_t)__bfloat16_as_ushort(lo);
}

// ===========================================================================
// Conversion pre-kernels
// ===========================================================================
__global__ void conv_x(const float* __restrict__ x) {
    size_t i = ((size_t)blockIdx.x * 256 + threadIdx.x) * 4;
    float4 v = *(const float4*)(x + i);
    __nv_bfloat16 h0 = __float2bfloat16(v.x), h1 = __float2bfloat16(v.y);
    __nv_bfloat16 h2 = __float2bfloat16(v.z), h3 = __float2bfloat16(v.w);
    __nv_bfloat16 l0 = __float2bfloat16(v.x - __bfloat162float(h0));
    __nv_bfloat16 l1 = __float2bfloat16(v.y - __bfloat162float(h1));
    __nv_bfloat16 l2 = __float2bfloat16(v.z - __bfloat162float(h2));
    __nv_bfloat16 l3 = __float2bfloat16(v.w - __bfloat162float(h3));
    *(uint2*)&g_xh[i] = make_uint2(pack2(h0, h1), pack2(h2, h3));
    *(uint2*)&g_xl[i] = make_uint2(pack2(l0, l1), pack2(l2, l3));
}

__global__ void conv_w(const float* __restrict__ Wq) {
    __shared__ float t[32][33];
    const int bx = blockIdx.x * 32, by = blockIdx.y * 32;
    const int tx = threadIdx.x, ty = threadIdx.y;
    #pragma unroll
    for (int j = 0; j < 4; j++)
        t[ty + 8 * j][tx] = Wq[(size_t)(by + ty + 8 * j) * DD + bx + tx];
    __syncthreads();
    #pragma unroll
    for (int j = 0; j < 4; j++) {
        float v = t[tx][ty + 8 * j];
        __nv_bfloat16 h = __float2bfloat16(v);
        __nv_bfloat16 l = __float2bfloat16(v - __bfloat162float(h));
        size_t o = (size_t)(bx + ty + 8 * j) * DD + by + tx;
        g_wh[o] = h;
        g_wl[o] = l;
    }
}

// ===========================================================================
// HMMA / cp.async helpers
// ===========================================================================
__device__ __forceinline__ uint32_t smem_u32(const void* p) {
    uint32_t a;
    asm("{ .reg .u64 t; cvta.to.shared.u64 t, %1; cvt.u32.u64 %0, t; }"
        : "=r"(a) : "l"(p));
    return a;
}

#define LDSM_X4(r0, r1, r2, r3, addr)                                         \
    asm volatile("ldmatrix.sync.aligned.m8n8.x4.shared.b16 {%0,%1,%2,%3}, [%4];" \
                 : "=r"(r0), "=r"(r1), "=r"(r2), "=r"(r3) : "r"(addr))

#define LDSM_T_X4(r0, r1, r2, r3, addr)                                       \
    asm volatile("ldmatrix.sync.aligned.m8n8.x4.trans.shared.b16 {%0,%1,%2,%3}, [%4];" \
                 : "=r"(r0), "=r"(r1), "=r"(r2), "=r"(r3) : "r"(addr))

__device__ __forceinline__ void mma16816(float* d, const uint32_t* a,
                                         uint32_t b0, uint32_t b1) {
    asm volatile(
        "mma.sync.aligned.m16n8k16.row.col.f32.bf16.bf16.f32 "
        "{%0,%1,%2,%3}, {%4,%5,%6,%7}, {%8,%9}, {%0,%1,%2,%3};"
        : "+f"(d[0]), "+f"(d[1]), "+f"(d[2]), "+f"(d[3])
        : "r"(a[0]), "r"(a[1]), "r"(a[2]), "r"(a[3]), "r"(b0), "r"(b1));
}

#define CPA(dst, src) \
    asm volatile("cp.async.cg.shared.global [%0], [%1], 16;" :: "r"(dst), "l"(src))
#define CPC() asm volatile("cp.async.commit_group;" ::: "memory")
#define CPW(n) asm volatile("cp.async.wait_group %0;" :: "n"(n) : "memory")

// ===========================================================================
// Projection GEMM on HMMA (K-layout epilogue only)
// ===========================================================================
static constexpr uint32_t JPITCH  = 144;
static constexpr uint32_t JXPLANE = 128 * JPITCH;
static constexpr uint32_t JP_WH   = 2 * JXPLANE;
static constexpr uint32_t JWPLANE = 64 * JPITCH;
static constexpr uint32_t JSTAGE  = JP_WH + 2 * JWPLANE;
static constexpr uint32_t PROJ_SMEM = 2 * JSTAGE;             // 110592

__device__ __forceinline__ void proj_prefetch(uint32_t st, int m0, int n0, int kc,
                                              int tid) {
    const __nv_bfloat16* xh = g_xh + (size_t)m0 * DD + kc * 64;
    const __nv_bfloat16* xl = g_xl + (size_t)m0 * DD + kc * 64;
    #pragma unroll
    for (int it = 0; it < 4; it++) {
        int idx = tid + it * 256;
        int row = idx >> 3, c = idx & 7;
        uint32_t d = (uint32_t)row * JPITCH + c * 16;
        CPA(st + d, (const char*)(xh + (size_t)row * DD + c * 8));
        CPA(st + JXPLANE + d, (const char*)(xl + (size_t)row * DD + c * 8));
    }
    const __nv_bfloat16* wh = g_wh + (size_t)n0 * DD + kc * 64;
    const __nv_bfloat16* wl = g_wl + (size_t)n0 * DD + kc * 64;
    #pragma unroll
    for (int it = 0; it < 2; it++) {
        int idx = tid + it * 256;
        int row = idx >> 3, c = idx & 7;
        uint32_t d = (uint32_t)row * JPITCH + c * 16;
        CPA(st + JP_WH + d, (const char*)(wh + (size_t)row * DD + c * 8));
        CPA(st + JP_WH + JWPLANE + d, (const char*)(wl + (size_t)row * DD + c * 8));
    }
}

__global__ void __launch_bounds__(256, 2) proj_hmma(int dummy) {
    extern __shared__ char smem[];
    const uint32_t sb = smem_u32(smem);
    const int tid = threadIdx.x;
    const int lane = tid & 31, w = tid >> 5;
    const int m0 = blockIdx.x * 128;
    const int h  = blockIdx.y;
    const int n0 = h * 64;

    proj_prefetch(sb, m0, n0, 0, tid);
    CPC();

    float acc[8][4] = {};
    const uint32_t arow = (uint32_t)(w * 16 + (lane & 15)) * JPITCH
                        + (uint32_t)(lane >> 4) * 16;
    const uint32_t wrow = JP_WH + (uint32_t)(lane & 7) * JPITCH
                        + (uint32_t)(lane >> 3) * 16;

    for (int kc = 0; kc < 8; kc++) {
        const uint32_t st = sb + (uint32_t)(kc & 1) * JSTAGE;
        if (kc + 1 < 8) {
            proj_prefetch(sb + (uint32_t)((kc + 1) & 1) * JSTAGE, m0, n0, kc + 1, tid);
            CPC();
            CPW(1);
        } else {
            CPW(0);
        }
        __syncthreads();

        uint32_t ah[4][4], al[4][4];
        #pragma unroll
        for (int i = 0; i < 4; i++) {
            LDSM_X4(ah[i][0], ah[i][1], ah[i][2], ah[i][3], st + arow + i * 32);
            LDSM_X4(al[i][0], al[i][1], al[i][2], al[i][3],
                    st + arow + JXPLANE + i * 32);
        }
        #pragma unroll
        for (int jj = 0; jj < 8; jj++) {
            uint32_t a = st + wrow + (uint32_t)jj * 8 * JPITCH;
            uint32_t bh_[8], bl_[8];
            LDSM_X4(bh_[0], bh_[1], bh_[2], bh_[3], a);
            LDSM_X4(bh_[4], bh_[5], bh_[6], bh_[7], a + 64);
            LDSM_X4(bl_[0], bl_[1], bl_[2], bl_[3], a + JWPLANE);
            LDSM_X4(bl_[4], bl_[5], bl_[6], bl_[7], a + JWPLANE + 64);
            #pragma unroll
            for (int i = 0; i < 4; i++) {
                mma16816(acc[jj], ah[i], bh_[2 * i], bh_[2 * i + 1]);
                mma16816(acc[jj], ah[i], bl_[2 * i], bl_[2 * i + 1]);
                mma16816(acc[jj], al[i], bh_[2 * i], bh_[2 * i + 1]);
            }
        }
        __syncthreads();
    }

    // ---- epilogue: split hi/lo; K-layout only (coalesced) ----
    const int r0g = m0 + w * 16 + (lane >> 2);
    const int b   = r0g >> 11;
    const int s0  = r0g & (SS - 1);
    const int bh_i = b * HH + h;
    const int c2  = (lane & 3) * 2;

    #pragma unroll
    for (int jj = 0; jj < 8; jj++) {
        int c = jj * 8 + c2;
        __nv_bfloat16 h0 = __float2bfloat16(acc[jj][0]);
        __nv_bfloat16 h1 = __float2bfloat16(acc[jj][1]);
        __nv_bfloat16 h2 = __float2bfloat16(acc[jj][2]);
        __nv_bfloat16 h3 = __float2bfloat16(acc[jj][3]);
        __nv_bfloat16 l0 = __float2bfloat16(acc[jj][0] - __bfloat162float(h0));
        __nv_bfloat16 l1 = __float2bfloat16(acc[jj][1] - __bfloat162float(h1));
        __nv_bfloat16 l2 = __float2bfloat16(acc[jj][2] - __bfloat162float(h2));
        __nv_bfloat16 l3 = __float2bfloat16(acc[jj][3] - __bfloat162float(h3));

        size_t ka = ((size_t)bh_i * SS + s0) * HD + c;
        *(uint32_t*)&g_kh[ka] = pack2(h0, h1);
        *(uint32_t*)&g_kl[ka] = pack2(l0, l1);
        *(uint32_t*)&g_kh[ka + 8 * HD] = pack2(h2, h3);
        *(uint32_t*)&g_kl[ka + 8 * HD] = pack2(l2, l3);
    }
}

// ===========================================================================
// Attention: HMMA flash, K-layout only (PV via ldmatrix.trans), 2 CTAs/SM.
// ===========================================================================
static constexpr uint32_t KPITCH  = 144;
static constexpr uint32_t KPLANE  = 128 * KPITCH;          // 18432
static constexpr uint32_t KSTAGE  = 2 * KPLANE;            // 36864 (hi, lo)
static constexpr uint32_t SMEM_BYTES = 2 * KSTAGE;         // 73728

__device__ __forceinline__ void prefetch_k(uint32_t stage_base,
                                           const __nv_bfloat16* kh,
                                           const __nv_bfloat16* kl, int tid) {
    #pragma unroll
    for (int it = 0; it < 4; it++) {
        int idx = tid + it * 256;
        int row = idx >> 3, c = idx & 7;
        uint32_t d = (uint32_t)row * KPITCH + c * 16;
        CPA(stage_base + d, (const char*)(kh + (size_t)row * HD + c * 8));
        CPA(stage_base + KPLANE + d, (const char*)(kl + (size_t)row * HD + c * 8));
    }
}

__global__ void __launch_bounds__(256, 2) attn_kernel(float* __restrict__ out) {
    extern __shared__ char smem[];
    const uint32_t sb = smem_u32(smem);
    const int tid = threadIdx.x;
    const int lane = tid & 31, w = tid >> 5;
    const int qb = blockIdx.x, h = blockIdx.y, b = blockIdx.z;
    const int bh = b * HH + h;
    const int NT = SS / 128;

    const __nv_bfloat16* khb = g_kh + (size_t)bh * SS * HD;
    const __nv_bfloat16* klb = g_kl + (size_t)bh * SS * HD;

    prefetch_k(sb, khb, klb, tid);
    CPC();

    // Q fragments straight from global (K-layout)
    uint32_t qh[4][4], ql[4][4];
    {
        const int r = lane >> 2, c2 = (lane & 3) * 2;
        const uint32_t* qhp = (const uint32_t*)(khb + (size_t)(qb * 128) * HD);
        const uint32_t* qlp = (const uint32_t*)(klb + (size_t)(qb * 128) * HD);
        #pragma unroll
        for (int kc = 0; kc < 4; kc++) {
            int base = (w * 16 + r) * HD + kc * 16 + c2;
            qh[kc][0] = qhp[(base              ) >> 1];
            qh[kc][1] = qhp[(base + 8 * HD     ) >> 1];
            qh[kc][2] = qhp[(base + 8          ) >> 1];
            qh[kc][3] = qhp[(base + 8 * HD + 8 ) >> 1];
            ql[kc][0] = qlp[(base              ) >> 1];
            ql[kc][1] = qlp[(base + 8 * HD     ) >> 1];
            ql[kc][2] = qlp[(base + 8          ) >> 1];
            ql[kc][3] = qlp[(base + 8 * HD + 8 ) >> 1];
        }
    }

    float O[8][4] = {};
    float l0 = 0.f, l1 = 0.f;

    const uint32_t krow = (uint32_t)(lane & 7) * KPITCH + (uint32_t)(lane >> 3) * 16;

    for (int kb = 0; kb < NT; kb++) {
        const uint32_t st = sb + (uint32_t)(kb & 1) * KSTAGE;

        // all warps finished reading stage (kb+1)&1 (during iter kb-1) -> refill it
        __syncthreads();
        if (kb + 1 < NT) {
            prefetch_k(sb + (uint32_t)((kb + 1) & 1) * KSTAGE,
                       khb + (size_t)(kb + 1) * 128 * HD,
                       klb + (size_t)(kb + 1) * 128 * HD, tid);
            CPC();
            CPW(1);        // K(kb) landed
        } else {
            CPW(0);
        }
        __syncthreads();

        // ---- S = Q K^T (3-pass, split into two accumulator chains) ----
        uint32_t ph[8][4];
        #pragma unroll
        for (int jj = 0; jj < 16; jj++) {
            uint32_t a = st + krow + (uint32_t)jj * 8 * KPITCH;
            uint32_t kh_[8], kl_[8];
            LDSM_X4(kh_[0], kh_[1], kh_[2], kh_[3], a);
            LDSM_X4(kh_[4], kh_[5], kh_[6], kh_[7], a + 64);
            LDSM_X4(kl_[0], kl_[1], kl_[2], kl_[3], a + KPLANE);
            LDSM_X4(kl_[4], kl_[5], kl_[6], kl_[7], a + KPLANE + 64);
            float Sa[4] = {}, Sb[4] = {};
            #pragma unroll
            for (int kc = 0; kc < 2; kc++) {
                mma16816(Sa, qh[kc], kh_[2 * kc], kh_[2 * kc + 1]);
                mma16816(Sa, qh[kc], kl_[2 * kc], kl_[2 * kc + 1]);
                mma16816(Sa, ql[kc], kh_[2 * kc], kh_[2 * kc + 1]);
            }
            #pragma unroll
            for (int kc = 2; kc < 4; kc++) {
                mma16816(Sb, qh[kc], kh_[2 * kc], kh_[2 * kc + 1]);
                mma16816(Sb, qh[kc], kl_[2 * kc], kl_[2 * kc + 1]);
                mma16816(Sb, ql[kc], kh_[2 * kc], kh_[2 * kc + 1]);
            }
            __nv_bfloat16 p0 = __float2bfloat16(__expf((Sa[0] + Sb[0]) * 0.125f));
            __nv_bfloat16 p1 = __float2bfloat16(__expf((Sa[1] + Sb[1]) * 0.125f));
            __nv_bfloat16 p2 = __float2bfloat16(__expf((Sa[2] + Sb[2]) * 0.125f));
            __nv_bfloat16 p3 = __float2bfloat16(__expf((Sa[3] + Sb[3]) * 0.125f));
            l0 += __bfloat162float(p0) + __bfloat162float(p1);
            l1 += __bfloat162float(p2) + __bfloat162float(p3);
            int kc = jj >> 1, o = (jj & 1) * 2;
            ph[kc][o]     = pack2(p0, p1);
            ph[kc][o + 1] = pack2(p2, p3);
        }

        // ---- O += P V : B-fragments via ldmatrix.trans on the SAME K tile ----
        // c32 outer / jj inner -> 8 independent O chains interleave
        #pragma unroll
        for (int c32 = 0; c32 < 4; c32++) {
            uint32_t rowa = st + (uint32_t)(c32 * 32 + lane) * KPITCH;
            #pragma unroll
            for (int jj = 0; jj < 8; jj++) {
                uint32_t a = rowa + (uint32_t)jj * 16;
                uint32_t th[4], tl[4];
                LDSM_T_X4(th[0], th[1], th[2], th[3], a);
                LDSM_T_X4(tl[0], tl[1], tl[2], tl[3], a + KPLANE);
                mma16816(O[jj], ph[2 * c32],     th[0], th[1]);
                mma16816(O[jj], ph[2 * c32],     tl[0], tl[1]);
                mma16816(O[jj], ph[2 * c32 + 1], th[2], th[3]);
                mma16816(O[jj], ph[2 * c32 + 1], tl[2], tl[3]);
            }
        }
    }

    // ---- epilogue ----
    l0 += __shfl_xor_sync(0xffffffffu, l0, 1);
    l0 += __shfl_xor_sync(0xffffffffu, l0, 2);
    l1 += __shfl_xor_sync(0xffffffffu, l1, 1);
    l1 += __shfl_xor_sync(0xffffffffu, l1, 2);
    float i0 = 1.f / l0, i1 = 1.f / l1;

    int r0 = qb * 128 + w * 16 + (lane >> 2);
    float* o0 = out + ((size_t)(b * SS + r0)) * DD + h * HD + (lane & 3) * 2;
    float* o1 = o0 + 8 * DD;
    #pragma unroll
    for (int jj = 0; jj < 8; jj++) {
        *(float2*)(o0 + jj * 8) = make_float2(O[jj][0] * i0, O[jj][1] * i0);
        *(float2*)(o1 + jj * 8) = make_float2(O[jj][2] * i1, O[jj][3] * i1);
    }
}

extern "C" void kernel_launch(void* const* d_in, const int* in_sizes, int n_in,
                              void* d_out, int out_size) {
    const float* x  = (const float*)d_in[0];
    const float* Wq = (const float*)d_in[1];
    float* out = (float*)d_out;

    cudaFuncSetAttribute(proj_hmma, cudaFuncAttributeMaxDynamicSharedMemorySize,
                         PROJ_SMEM);
    cudaFuncSetAttribute(attn_kernel, cudaFuncAttributeMaxDynamicSharedMemorySize,
                         SMEM_BYTES);

    conv_x<<<(BB * SS * DD) / (256 * 4), 256>>>(x);
    conv_w<<<dim3(DD / 32, DD / 32), dim3(32, 8)>>>(Wq);
    proj_hmma<<<dim3((BB * SS) / 128, HH), 256, PROJ_SMEM>>>(0);
    attn_kernel<<<dim3(SS / 128, HH, BB), 256, SMEM_BYTES>>>(out);
}